// round 1
// baseline (speedup 1.0000x reference)
#include <cuda_runtime.h>

#define H     64
#define TILE  128
#define PAD   65
#define MAXN  100000

// Scratch (allocation-free rule: __device__ globals). Zero-initialized at load;
// node_kernel re-zeros g_agg after consuming it, so every graph replay sees zeros.
__device__ float g_x[MAXN * H];
__device__ float g_agg[MAXN * H];

// x = node_emb[z]
__global__ __launch_bounds__(256) void init_kernel(const float* __restrict__ node_emb,
                                                   const int* __restrict__ z, int n) {
    int t = blockIdx.x * 256 + threadIdx.x;           // one float4 per thread
    int total = n * (H / 4);
    if (t >= total) return;
    int node = t >> 4;
    int p    = t & 15;
    int zi   = __ldg(z + node);
    float4 v = ((const float4*)node_emb)[zi * 16 + p];
    ((float4*)g_x)[(size_t)node * 16 + p] = v;
}

// msg = relu(x[src] + edge_attr); scatter-add (vector RED) into g_agg[dst]
__global__ __launch_bounds__(256) void edge_kernel(const float* __restrict__ ea,
                                                   const int* __restrict__ src,
                                                   const int* __restrict__ dst, int E) {
    int t = blockIdx.x * 256 + threadIdx.x;           // 16 threads per edge
    if (t >= E * 16) return;
    int e = t >> 4;
    int p = t & 15;
    int s = __ldg(src + e);
    int d = __ldg(dst + e);
    float4 a  = ((const float4*)ea)[(size_t)e * 16 + p];
    float4 xv = ((const float4*)g_x)[(size_t)s * 16 + p];
    float4 m = make_float4(fmaxf(a.x + xv.x, 0.f),
                           fmaxf(a.y + xv.y, 0.f),
                           fmaxf(a.z + xv.z, 0.f),
                           fmaxf(a.w + xv.w, 0.f));
    float* o = g_agg + ((size_t)d << 6) + (p << 2);
    asm volatile("red.global.add.v4.f32 [%0], {%1, %2, %3, %4};"
                 :: "l"(o), "f"(m.x), "f"(m.y), "f"(m.z), "f"(m.w)
                 : "memory");
}

// Per-node: in = agg + x; h1 = relu(W1 in + b1); h2 = W2 h1 + b2;
// (relu if not last conv); out = h2 + x.  Also re-zeros g_agg.
// Layout: one thread per node; activations in registers; W broadcast from smem.
__global__ __launch_bounds__(TILE) void node_kernel(const float* __restrict__ W1g,
                                                    const float* __restrict__ b1g,
                                                    const float* __restrict__ W2g,
                                                    const float* __restrict__ b2g,
                                                    int n, int relu_out,
                                                    float* __restrict__ dout, int last) {
    extern __shared__ float sm[];
    float* sW1 = sm;                       // 4096
    float* sW2 = sm + H * H;               // 4096
    float* sb1 = sm + 2 * H * H;           // 64
    float* sb2 = sb1 + H;                  // 64
    float* sX  = sb2 + H;                  // TILE*PAD (x tile / output staging)
    float* sT  = sX + TILE * PAD;          // TILE*PAD (agg tile / h1 staging)

    int tid = threadIdx.x;

    for (int idx = tid; idx < H * H; idx += TILE) {
        sW1[idx] = W1g[idx];
        sW2[idx] = W2g[idx];
    }
    if (tid < H) { sb1[tid] = b1g[tid]; sb2[tid] = b2g[tid]; }

    int base = blockIdx.x * TILE;

    // Coalesced tile load (and g_agg zeroing for the next conv / next replay)
    for (int idx = tid; idx < TILE * (H / 4); idx += TILE) {
        int row = idx >> 4;
        int c   = (idx & 15) << 2;
        int g   = base + row;
        float4 xv = make_float4(0.f, 0.f, 0.f, 0.f);
        float4 av = xv;
        if (g < n) {
            size_t off = (size_t)g * H + c;
            xv = *(const float4*)(g_x + off);
            av = *(const float4*)(g_agg + off);
            *(float4*)(g_agg + off) = make_float4(0.f, 0.f, 0.f, 0.f);
        }
        float* px = sX + row * PAD + c;
        px[0] = xv.x; px[1] = xv.y; px[2] = xv.z; px[3] = xv.w;
        float* pt = sT + row * PAD + c;
        pt[0] = av.x; pt[1] = av.y; pt[2] = av.z; pt[3] = av.w;
    }
    __syncthreads();

    int r = tid;                           // this thread's node row
    float in[H];
    #pragma unroll
    for (int k = 0; k < H; ++k) in[k] = sX[r * PAD + k] + sT[r * PAD + k];

    // Layer 1: h1 = relu(W1 in + b1) -> staged into sT (own row only, no sync needed)
    #pragma unroll 4
    for (int j = 0; j < H; ++j) {
        float acc = sb1[j];
        const float4* w = (const float4*)(sW1 + j * H);
        #pragma unroll
        for (int k4 = 0; k4 < H / 4; ++k4) {
            float4 wv = w[k4];               // uniform across lanes -> broadcast LDS
            acc = fmaf(in[4 * k4 + 0], wv.x, acc);
            acc = fmaf(in[4 * k4 + 1], wv.y, acc);
            acc = fmaf(in[4 * k4 + 2], wv.z, acc);
            acc = fmaf(in[4 * k4 + 3], wv.w, acc);
        }
        sT[r * PAD + j] = fmaxf(acc, 0.f);
    }

    #pragma unroll
    for (int k = 0; k < H; ++k) in[k] = sT[r * PAD + k];

    // Layer 2 + optional relu + residual; result overwrites own sX row
    #pragma unroll 4
    for (int j = 0; j < H; ++j) {
        float acc = sb2[j];
        const float4* w = (const float4*)(sW2 + j * H);
        #pragma unroll
        for (int k4 = 0; k4 < H / 4; ++k4) {
            float4 wv = w[k4];
            acc = fmaf(in[4 * k4 + 0], wv.x, acc);
            acc = fmaf(in[4 * k4 + 1], wv.y, acc);
            acc = fmaf(in[4 * k4 + 2], wv.z, acc);
            acc = fmaf(in[4 * k4 + 3], wv.w, acc);
        }
        if (relu_out) acc = fmaxf(acc, 0.f);
        acc += sX[r * PAD + j];
        sX[r * PAD + j] = acc;
    }
    __syncthreads();

    // Coalesced store of the new x
    float* xout = last ? dout : g_x;
    for (int idx = tid; idx < TILE * (H / 4); idx += TILE) {
        int row = idx >> 4;
        int c   = (idx & 15) << 2;
        int g   = base + row;
        if (g < n) {
            float* p = sX + row * PAD + c;
            float4 v = make_float4(p[0], p[1], p[2], p[3]);
            *(float4*)(xout + (size_t)g * H + c) = v;
        }
    }
}

static const int NODE_SMEM_BYTES = (2 * H * H + 2 * H + 2 * TILE * PAD) * (int)sizeof(float);

extern "C" void kernel_launch(void* const* d_in, const int* in_sizes, int n_in,
                              void* d_out, int out_size) {
    const float* node_emb  = (const float*)d_in[0];
    const float* W1        = (const float*)d_in[1];
    const float* b1        = (const float*)d_in[2];
    const float* W2        = (const float*)d_in[3];
    const float* b2        = (const float*)d_in[4];
    const float* edge_attr = (const float*)d_in[5];
    const int*   z         = (const int*)d_in[6];
    const int*   eidx      = (const int*)d_in[7];

    int n = in_sizes[6];        // 100000 nodes
    int E = in_sizes[7] / 2;    // 1000000 edges
    float* out = (float*)d_out;

    cudaFuncSetAttribute(node_kernel, cudaFuncAttributeMaxDynamicSharedMemorySize,
                         NODE_SMEM_BYTES);

    init_kernel<<<(n * (H / 4) + 255) / 256, 256>>>(node_emb, z, n);

    int node_blocks = (n + TILE - 1) / TILE;
    int edge_blocks = (E * 16 + 255) / 256;

    for (int i = 0; i < 3; ++i) {
        edge_kernel<<<edge_blocks, 256>>>(edge_attr, eidx, eidx + E, E);
        node_kernel<<<node_blocks, TILE, NODE_SMEM_BYTES>>>(
            W1 + i * H * H, b1 + i * H, W2 + i * H * H, b2 + i * H,
            n, /*relu_out=*/(i < 2) ? 1 : 0, out, /*last=*/(i == 2) ? 1 : 0);
    }
}

// round 2
// speedup vs baseline: 1.0031x; 1.0031x over previous
#include <cuda_runtime.h>

#define H     64
#define TILE  128
#define PAD   66
#define MAXN  100000

// Scratch (allocation-free rule). Zero-init at load; node_kernel re-zeros g_agg
// after consuming it, so every graph replay sees zeros.
__device__ float g_x[MAXN * H];
__device__ float g_agg[MAXN * H];

// ---- packed fp32x2 helpers (Blackwell fma.rn.f32x2, PTX-only) ----
__device__ __forceinline__ unsigned long long ffma2(unsigned long long a,
                                                    unsigned long long b,
                                                    unsigned long long c) {
    unsigned long long d;
    asm("fma.rn.f32x2 %0, %1, %2, %3;" : "=l"(d) : "l"(a), "l"(b), "l"(c));
    return d;
}
__device__ __forceinline__ unsigned long long pk2(float x, float y) {
    unsigned long long r;
    asm("mov.b64 %0, {%1, %2};" : "=l"(r) : "f"(x), "f"(y));
    return r;
}
__device__ __forceinline__ float2 upk2(unsigned long long v) {
    float2 r;
    asm("mov.b64 {%0, %1}, %2;" : "=f"(r.x), "=f"(r.y) : "l"(v));
    return r;
}

// x = node_emb[z]
__global__ __launch_bounds__(256) void init_kernel(const float* __restrict__ node_emb,
                                                   const int* __restrict__ z, int n) {
    int t = blockIdx.x * 256 + threadIdx.x;           // one float4 per thread
    int total = n * (H / 4);
    if (t >= total) return;
    int node = t >> 4;
    int p    = t & 15;
    int zi   = __ldg(z + node);
    float4 v = ((const float4*)node_emb)[zi * 16 + p];
    ((float4*)g_x)[(size_t)node * 16 + p] = v;
}

// msg = relu(x[src] + edge_attr); scatter-add (vector RED) into g_agg[dst].
// 4 threads per edge; all loads batched BEFORE any RED (the red asm's memory
// clobber would otherwise serialize loads behind stores).
__global__ __launch_bounds__(256) void edge_kernel(const float* __restrict__ ea,
                                                   const int* __restrict__ src,
                                                   const int* __restrict__ dst, int E) {
    int t = blockIdx.x * 256 + threadIdx.x;
    if (t >= E * 4) return;
    int e = t >> 2;
    int q = (t & 3) << 2;                 // float4 slot base: q..q+3 of 16
    int s = __ldg(src + e);
    int d = __ldg(dst + e);
    const float4* pa = (const float4*)ea  + (size_t)e * 16 + q;
    const float4* px = (const float4*)g_x + (size_t)s * 16 + q;

    float4 a0 = pa[0], a1 = pa[1], a2 = pa[2], a3 = pa[3];
    float4 x0 = px[0], x1 = px[1], x2 = px[2], x3 = px[3];

    float4 m0 = make_float4(fmaxf(a0.x + x0.x, 0.f), fmaxf(a0.y + x0.y, 0.f),
                            fmaxf(a0.z + x0.z, 0.f), fmaxf(a0.w + x0.w, 0.f));
    float4 m1 = make_float4(fmaxf(a1.x + x1.x, 0.f), fmaxf(a1.y + x1.y, 0.f),
                            fmaxf(a1.z + x1.z, 0.f), fmaxf(a1.w + x1.w, 0.f));
    float4 m2 = make_float4(fmaxf(a2.x + x2.x, 0.f), fmaxf(a2.y + x2.y, 0.f),
                            fmaxf(a2.z + x2.z, 0.f), fmaxf(a2.w + x2.w, 0.f));
    float4 m3 = make_float4(fmaxf(a3.x + x3.x, 0.f), fmaxf(a3.y + x3.y, 0.f),
                            fmaxf(a3.z + x3.z, 0.f), fmaxf(a3.w + x3.w, 0.f));

    float* o = g_agg + ((size_t)d << 6) + (q << 2);
    asm volatile("red.global.add.v4.f32 [%0], {%1, %2, %3, %4};"
                 :: "l"(o),      "f"(m0.x), "f"(m0.y), "f"(m0.z), "f"(m0.w) : "memory");
    asm volatile("red.global.add.v4.f32 [%0], {%1, %2, %3, %4};"
                 :: "l"(o + 4),  "f"(m1.x), "f"(m1.y), "f"(m1.z), "f"(m1.w) : "memory");
    asm volatile("red.global.add.v4.f32 [%0], {%1, %2, %3, %4};"
                 :: "l"(o + 8),  "f"(m2.x), "f"(m2.y), "f"(m2.z), "f"(m2.w) : "memory");
    asm volatile("red.global.add.v4.f32 [%0], {%1, %2, %3, %4};"
                 :: "l"(o + 12), "f"(m3.x), "f"(m3.y), "f"(m3.z), "f"(m3.w) : "memory");
}

// Per-node MLP. One thread per node; packed f32x2 FMAs; single smem tile.
// in = x + agg (computed during load); residual x re-read from g_x at store.
// Also re-zeros g_agg for next conv / next replay.
__global__ __launch_bounds__(TILE, 3) void node_kernel(const float* __restrict__ W1g,
                                                       const float* __restrict__ b1g,
                                                       const float* __restrict__ W2g,
                                                       const float* __restrict__ b2g,
                                                       int n, int relu_out,
                                                       float* __restrict__ dout, int last) {
    extern __shared__ float sm[];
    float* sW1 = sm;                        // 4096
    float* sW2 = sm + H * H;                // 4096
    float* sb1 = sm + 2 * H * H;            // 64
    float* sb2 = sb1 + H;                   // 64
    float* sT  = sb2 + H;                   // TILE*PAD

    int tid = threadIdx.x;

    for (int idx = tid; idx < H * H; idx += TILE) {
        sW1[idx] = W1g[idx];
        sW2[idx] = W2g[idx];
    }
    if (tid < H) { sb1[tid] = b1g[tid]; sb2[tid] = b2g[tid]; }

    int base = blockIdx.x * TILE;

    // Load (x + agg) tile coalesced; zero g_agg.
    for (int idx = tid; idx < TILE * (H / 4); idx += TILE) {
        int row = idx >> 4;
        int c   = (idx & 15) << 2;
        int g   = base + row;
        float4 v = make_float4(0.f, 0.f, 0.f, 0.f);
        if (g < n) {
            size_t off = (size_t)g * H + c;
            float4 xv = *(const float4*)(g_x + off);
            float4 av = *(const float4*)(g_agg + off);
            *(float4*)(g_agg + off) = make_float4(0.f, 0.f, 0.f, 0.f);
            v = make_float4(xv.x + av.x, xv.y + av.y, xv.z + av.z, xv.w + av.w);
        }
        float* p = sT + row * PAD + c;
        p[0] = v.x; p[1] = v.y; p[2] = v.z; p[3] = v.w;
    }
    __syncthreads();

    int r = tid;
    const float* myrow = sT + r * PAD;      // r*PAD even -> 8B aligned

    unsigned long long in2[H / 2];
    #pragma unroll
    for (int k2 = 0; k2 < H / 2; ++k2)
        in2[k2] = *(const unsigned long long*)(myrow + 2 * k2);

    // Layer 1: h1 = relu(W1 in + b1) -> stage into own sT row (regs hold in2)
    #pragma unroll 2
    for (int j = 0; j < H; ++j) {
        const unsigned long long* w2 = (const unsigned long long*)(sW1 + j * H);
        unsigned long long a0 = pk2(sb1[j], 0.f);
        unsigned long long a1 = pk2(0.f, 0.f);
        #pragma unroll
        for (int k2 = 0; k2 < H / 2; k2 += 2) {
            a0 = ffma2(in2[k2],     w2[k2],     a0);
            a1 = ffma2(in2[k2 + 1], w2[k2 + 1], a1);
        }
        float2 f0 = upk2(a0), f1 = upk2(a1);
        sT[r * PAD + j] = fmaxf((f0.x + f0.y) + (f1.x + f1.y), 0.f);
    }

    #pragma unroll
    for (int k2 = 0; k2 < H / 2; ++k2)
        in2[k2] = *(const unsigned long long*)(myrow + 2 * k2);

    // Layer 2 (+ optional relu), residual added at store time
    #pragma unroll 2
    for (int j = 0; j < H; ++j) {
        const unsigned long long* w2 = (const unsigned long long*)(sW2 + j * H);
        unsigned long long a0 = pk2(sb2[j], 0.f);
        unsigned long long a1 = pk2(0.f, 0.f);
        #pragma unroll
        for (int k2 = 0; k2 < H / 2; k2 += 2) {
            a0 = ffma2(in2[k2],     w2[k2],     a0);
            a1 = ffma2(in2[k2 + 1], w2[k2 + 1], a1);
        }
        float2 f0 = upk2(a0), f1 = upk2(a1);
        float acc = (f0.x + f0.y) + (f1.x + f1.y);
        if (relu_out) acc = fmaxf(acc, 0.f);
        sT[r * PAD + j] = acc;
    }
    __syncthreads();

    // Coalesced store: out = h2 + x (residual re-read from g_x, L2-hot)
    float* xout = last ? dout : g_x;
    for (int idx = tid; idx < TILE * (H / 4); idx += TILE) {
        int row = idx >> 4;
        int c   = (idx & 15) << 2;
        int g   = base + row;
        if (g < n) {
            size_t off = (size_t)g * H + c;
            float4 xv = *(const float4*)(g_x + off);
            float* p = sT + row * PAD + c;
            float4 v = make_float4(p[0] + xv.x, p[1] + xv.y, p[2] + xv.z, p[3] + xv.w);
            *(float4*)(xout + off) = v;
        }
    }
}

static const int NODE_SMEM_BYTES = (2 * H * H + 2 * H + TILE * PAD) * (int)sizeof(float);

extern "C" void kernel_launch(void* const* d_in, const int* in_sizes, int n_in,
                              void* d_out, int out_size) {
    const float* node_emb  = (const float*)d_in[0];
    const float* W1        = (const float*)d_in[1];
    const float* b1        = (const float*)d_in[2];
    const float* W2        = (const float*)d_in[3];
    const float* b2        = (const float*)d_in[4];
    const float* edge_attr = (const float*)d_in[5];
    const int*   z         = (const int*)d_in[6];
    const int*   eidx      = (const int*)d_in[7];

    int n = in_sizes[6];        // 100000 nodes
    int E = in_sizes[7] / 2;    // 1000000 edges
    float* out = (float*)d_out;

    cudaFuncSetAttribute(node_kernel, cudaFuncAttributeMaxDynamicSharedMemorySize,
                         NODE_SMEM_BYTES);

    init_kernel<<<(n * (H / 4) + 255) / 256, 256>>>(node_emb, z, n);

    int node_blocks = (n + TILE - 1) / TILE;
    int edge_blocks = (E * 4 + 255) / 256;

    for (int i = 0; i < 3; ++i) {
        edge_kernel<<<edge_blocks, 256>>>(edge_attr, eidx, eidx + E, E);
        node_kernel<<<node_blocks, TILE, NODE_SMEM_BYTES>>>(
            W1 + i * H * H, b1 + i * H, W2 + i * H * H, b2 + i * H,
            n, /*relu_out=*/(i < 2) ? 1 : 0, out, /*last=*/(i == 2) ? 1 : 0);
    }
}

// round 3
// speedup vs baseline: 1.0833x; 1.0799x over previous
#include <cuda_runtime.h>

#define H     64
#define NT    256          // node kernel threads / nodes per block
#define PAD   66
#define MAXN  100000

// Scratch (allocation-free rule). Zero-init at load; node_kernel re-zeros g_agg
// after consuming it, so every graph replay sees zeros.
__device__ float g_x[MAXN * H];
__device__ float g_agg[MAXN * H];

// ---- packed fp32x2 helpers (Blackwell FFMA2, PTX-only) ----
typedef unsigned long long u64;
__device__ __forceinline__ u64 ffma2(u64 a, u64 b, u64 c) {
    u64 d; asm("fma.rn.f32x2 %0, %1, %2, %3;" : "=l"(d) : "l"(a), "l"(b), "l"(c));
    return d;
}
__device__ __forceinline__ u64 addf2(u64 a, u64 b) {
    u64 d; asm("add.rn.f32x2 %0, %1, %2;" : "=l"(d) : "l"(a), "l"(b));
    return d;
}
__device__ __forceinline__ float2 upk2(u64 v) {
    float2 r; asm("mov.b64 {%0, %1}, %2;" : "=f"(r.x), "=f"(r.y) : "l"(v));
    return r;
}

// x = node_emb[z], split in two kernels purely so ncu -s 5 lands on node_kernel.
__global__ __launch_bounds__(256) void init_kernel(const float* __restrict__ node_emb,
                                                   const int* __restrict__ z,
                                                   int lo, int hi) {
    int t = blockIdx.x * 256 + threadIdx.x;
    int total = (hi - lo) * (H / 4);
    if (t >= total) return;
    int node = lo + (t >> 4);
    int p    = t & 15;
    int zi   = __ldg(z + node);
    float4 v = ((const float4*)node_emb)[zi * 16 + p];
    ((float4*)g_x)[(size_t)node * 16 + p] = v;
}

// msg = relu(x[src] + edge_attr); vector-RED scatter into g_agg[dst].
// R1 coalesced layout (16 threads/edge, one float4 each); 2 edges per thread
// to batch loads ahead of the REDs and amortize index loads.
__global__ __launch_bounds__(256) void edge_kernel(const float* __restrict__ ea,
                                                   const int* __restrict__ src,
                                                   const int* __restrict__ dst, int E) {
    int half = E >> 1;
    int t = blockIdx.x * 256 + threadIdx.x;
    if (t >= half * 16) return;
    int e1 = t >> 4;
    int p  = t & 15;
    int e2 = e1 + half;

    int s1 = __ldg(src + e1), d1 = __ldg(dst + e1);
    int s2 = __ldg(src + e2), d2 = __ldg(dst + e2);

    float4 a1 = ((const float4*)ea)[(size_t)e1 * 16 + p];
    float4 a2 = ((const float4*)ea)[(size_t)e2 * 16 + p];
    float4 x1 = ((const float4*)g_x)[(size_t)s1 * 16 + p];
    float4 x2 = ((const float4*)g_x)[(size_t)s2 * 16 + p];

    float4 m1 = make_float4(fmaxf(a1.x + x1.x, 0.f), fmaxf(a1.y + x1.y, 0.f),
                            fmaxf(a1.z + x1.z, 0.f), fmaxf(a1.w + x1.w, 0.f));
    float4 m2 = make_float4(fmaxf(a2.x + x2.x, 0.f), fmaxf(a2.y + x2.y, 0.f),
                            fmaxf(a2.z + x2.z, 0.f), fmaxf(a2.w + x2.w, 0.f));

    float* o1 = g_agg + ((size_t)d1 << 6) + (p << 2);
    float* o2 = g_agg + ((size_t)d2 << 6) + (p << 2);
    asm volatile("red.global.add.v4.f32 [%0], {%1, %2, %3, %4};"
                 :: "l"(o1), "f"(m1.x), "f"(m1.y), "f"(m1.z), "f"(m1.w) : "memory");
    asm volatile("red.global.add.v4.f32 [%0], {%1, %2, %3, %4};"
                 :: "l"(o2), "f"(m2.x), "f"(m2.y), "f"(m2.z), "f"(m2.w) : "memory");
}

// Per-node MLP, one thread per node. Weights in smem, loaded as ulonglong2
// (LDS.128, no pack movs); 4 independent ffma2 chains per output.
__global__ __launch_bounds__(NT, 2) void node_kernel(const float* __restrict__ W1g,
                                                     const float* __restrict__ b1g,
                                                     const float* __restrict__ W2g,
                                                     const float* __restrict__ b2g,
                                                     int n, int relu_out,
                                                     float* __restrict__ dout, int last) {
    extern __shared__ float sm[];
    float* sW1 = sm;                        // 4096 floats
    float* sW2 = sm + H * H;                // 4096
    float* sb1 = sm + 2 * H * H;            // 64
    float* sb2 = sb1 + H;                   // 64
    float* sT  = sb2 + H;                   // NT*PAD

    int tid = threadIdx.x;

    for (int idx = tid; idx < H * H; idx += NT) {
        sW1[idx] = W1g[idx];
        sW2[idx] = W2g[idx];
    }
    if (tid < H) { sb1[tid] = b1g[tid]; sb2[tid] = b2g[tid]; }

    int base = blockIdx.x * NT;

    // Coalesced load of (x + agg) tile; zero g_agg for next conv / next replay.
    for (int idx = tid; idx < NT * (H / 4); idx += NT) {
        int row = idx >> 4;
        int c   = (idx & 15) << 2;
        int g   = base + row;
        float4 v = make_float4(0.f, 0.f, 0.f, 0.f);
        if (g < n) {
            size_t off = (size_t)g * H + c;
            float4 xv = *(const float4*)(g_x + off);
            float4 av = *(const float4*)(g_agg + off);
            *(float4*)(g_agg + off) = make_float4(0.f, 0.f, 0.f, 0.f);
            v = make_float4(xv.x + av.x, xv.y + av.y, xv.z + av.z, xv.w + av.w);
        }
        float* p = sT + row * PAD + c;
        p[0] = v.x; p[1] = v.y; p[2] = v.z; p[3] = v.w;
    }
    __syncthreads();

    int r = tid;
    float* myrow = sT + r * PAD;            // r*PAD even -> 8B aligned

    u64 in2[H / 2];
    #pragma unroll
    for (int k2 = 0; k2 < H / 2; ++k2)
        in2[k2] = *(const u64*)(myrow + 2 * k2);

    // Layer 1: h1 = relu(W1 in + b1), staged back into own sT row.
    #pragma unroll 2
    for (int j = 0; j < H; ++j) {
        const ulonglong2* w = (const ulonglong2*)(sW1 + j * H);
        u64 a0 = 0ull, a1 = 0ull, a2 = 0ull, a3 = 0ull;
        #pragma unroll
        for (int k8 = 0; k8 < H / 8; ++k8) {
            ulonglong2 wA = w[2 * k8];       // LDS.128 broadcast
            ulonglong2 wB = w[2 * k8 + 1];
            a0 = ffma2(in2[4 * k8 + 0], wA.x, a0);
            a1 = ffma2(in2[4 * k8 + 1], wA.y, a1);
            a2 = ffma2(in2[4 * k8 + 2], wB.x, a2);
            a3 = ffma2(in2[4 * k8 + 3], wB.y, a3);
        }
        float2 f = upk2(addf2(addf2(a0, a1), addf2(a2, a3)));
        myrow[j] = fmaxf(f.x + f.y + sb1[j], 0.f);
    }

    #pragma unroll
    for (int k2 = 0; k2 < H / 2; ++k2)
        in2[k2] = *(const u64*)(myrow + 2 * k2);

    // Layer 2 (+ optional relu); residual added at store time.
    #pragma unroll 2
    for (int j = 0; j < H; ++j) {
        const ulonglong2* w = (const ulonglong2*)(sW2 + j * H);
        u64 a0 = 0ull, a1 = 0ull, a2 = 0ull, a3 = 0ull;
        #pragma unroll
        for (int k8 = 0; k8 < H / 8; ++k8) {
            ulonglong2 wA = w[2 * k8];
            ulonglong2 wB = w[2 * k8 + 1];
            a0 = ffma2(in2[4 * k8 + 0], wA.x, a0);
            a1 = ffma2(in2[4 * k8 + 1], wA.y, a1);
            a2 = ffma2(in2[4 * k8 + 2], wB.x, a2);
            a3 = ffma2(in2[4 * k8 + 3], wB.y, a3);
        }
        float2 f = upk2(addf2(addf2(a0, a1), addf2(a2, a3)));
        float acc = f.x + f.y + sb2[j];
        if (relu_out) acc = fmaxf(acc, 0.f);
        myrow[j] = acc;
    }
    __syncthreads();

    // Coalesced store: out = h2 + x (residual re-read from g_x, L2-hot).
    float* xout = last ? dout : g_x;
    for (int idx = tid; idx < NT * (H / 4); idx += NT) {
        int row = idx >> 4;
        int c   = (idx & 15) << 2;
        int g   = base + row;
        if (g < n) {
            size_t off = (size_t)g * H + c;
            float4 xv = *(const float4*)(g_x + off);
            float* p = sT + row * PAD + c;
            float4 v = make_float4(p[0] + xv.x, p[1] + xv.y, p[2] + xv.z, p[3] + xv.w);
            *(float4*)(xout + off) = v;
        }
    }
}

static const int NODE_SMEM_BYTES = (2 * H * H + 2 * H + NT * PAD) * (int)sizeof(float);

extern "C" void kernel_launch(void* const* d_in, const int* in_sizes, int n_in,
                              void* d_out, int out_size) {
    const float* node_emb  = (const float*)d_in[0];
    const float* W1        = (const float*)d_in[1];
    const float* b1        = (const float*)d_in[2];
    const float* W2        = (const float*)d_in[3];
    const float* b2        = (const float*)d_in[4];
    const float* edge_attr = (const float*)d_in[5];
    const int*   z         = (const int*)d_in[6];
    const int*   eidx      = (const int*)d_in[7];

    int n = in_sizes[6];        // 100000 nodes
    int E = in_sizes[7] / 2;    // 1000000 edges
    float* out = (float*)d_out;

    cudaFuncSetAttribute(node_kernel, cudaFuncAttributeMaxDynamicSharedMemorySize,
                         NODE_SMEM_BYTES);

    // Two init launches so launch index 5 (ncu -s 5 -c 1) is a node_kernel.
    int nh = n / 2;
    init_kernel<<<(nh * (H / 4) + 255) / 256, 256>>>(node_emb, z, 0, nh);
    init_kernel<<<((n - nh) * (H / 4) + 255) / 256, 256>>>(node_emb, z, nh, n);

    int node_blocks = (n + NT - 1) / NT;
    int edge_blocks = ((E / 2) * 16 + 255) / 256;

    for (int i = 0; i < 3; ++i) {
        edge_kernel<<<edge_blocks, 256>>>(edge_attr, eidx, eidx + E, E);
        node_kernel<<<node_blocks, NT, NODE_SMEM_BYTES>>>(
            W1 + i * H * H, b1 + i * H, W2 + i * H * H, b2 + i * H,
            n, /*relu_out=*/(i < 2) ? 1 : 0, out, /*last=*/(i == 2) ? 1 : 0);
    }
}

// round 4
// speedup vs baseline: 1.2797x; 1.1813x over previous
#include <cuda_runtime.h>

#define H     64
#define NPB   128          // nodes per block (node kernel tile)
#define NT    256
#define MAXN  100000
#define SROW  136          // smem activation row stride (floats)
#define WROW  68           // smem transposed-weight row stride

// Scratch (allocation-free rule). node_kernel re-zeros g_agg after consuming
// it, so every graph replay sees zeros.
__device__ float g_x[MAXN * H];
__device__ float g_agg[MAXN * H];

typedef unsigned long long u64;
__device__ __forceinline__ u64 ffma2(u64 a, u64 b, u64 c) {
    u64 d; asm("fma.rn.f32x2 %0, %1, %2, %3;" : "=l"(d) : "l"(a), "l"(b), "l"(c));
    return d;
}
__device__ __forceinline__ u64 pk2(float x, float y) {
    u64 r; asm("mov.b64 %0, {%1, %2};" : "=l"(r) : "f"(x), "f"(y));
    return r;
}
__device__ __forceinline__ float2 upk2(u64 v) {
    float2 r; asm("mov.b64 {%0, %1}, %2;" : "=f"(r.x), "=f"(r.y) : "l"(v));
    return r;
}

// k-major activation layout with 8-float-chunk rotation so that transposed
// STS spreads banks while per-k GEMM loads stay 2-address broadcasts.
__device__ __forceinline__ int swiz(int k, int n) {
    return k * SROW + ((n + ((k >> 2) << 3)) & 127);
}

// x = node_emb[z], split in two so ncu -s 5 -c 1 lands on a node_kernel.
__global__ __launch_bounds__(256) void init_kernel(const float* __restrict__ node_emb,
                                                   const int* __restrict__ z,
                                                   int lo, int hi) {
    int t = blockIdx.x * 256 + threadIdx.x;
    int total = (hi - lo) * (H / 4);
    if (t >= total) return;
    int node = lo + (t >> 4);
    int p    = t & 15;
    int zi   = __ldg(z + node);
    float4 v = ((const float4*)node_emb)[zi * 16 + p];
    ((float4*)g_x)[(size_t)node * 16 + p] = v;
}

// msg = relu(x[src] + edge_attr); vector-RED scatter into g_agg[dst].
// Coalesced 16-threads/edge layout; 2 edges/thread, loads batched before REDs.
__global__ __launch_bounds__(256) void edge_kernel(const float* __restrict__ ea,
                                                   const int* __restrict__ src,
                                                   const int* __restrict__ dst, int E) {
    int half = E >> 1;
    int t = blockIdx.x * 256 + threadIdx.x;
    if (t >= half * 16) return;
    int e1 = t >> 4;
    int p  = t & 15;
    int e2 = e1 + half;

    int s1 = __ldg(src + e1), d1 = __ldg(dst + e1);
    int s2 = __ldg(src + e2), d2 = __ldg(dst + e2);

    float4 a1 = ((const float4*)ea)[(size_t)e1 * 16 + p];
    float4 a2 = ((const float4*)ea)[(size_t)e2 * 16 + p];
    float4 x1 = ((const float4*)g_x)[(size_t)s1 * 16 + p];
    float4 x2 = ((const float4*)g_x)[(size_t)s2 * 16 + p];

    float4 m1 = make_float4(fmaxf(a1.x + x1.x, 0.f), fmaxf(a1.y + x1.y, 0.f),
                            fmaxf(a1.z + x1.z, 0.f), fmaxf(a1.w + x1.w, 0.f));
    float4 m2 = make_float4(fmaxf(a2.x + x2.x, 0.f), fmaxf(a2.y + x2.y, 0.f),
                            fmaxf(a2.z + x2.z, 0.f), fmaxf(a2.w + x2.w, 0.f));

    float* o1 = g_agg + ((size_t)d1 << 6) + (p << 2);
    float* o2 = g_agg + ((size_t)d2 << 6) + (p << 2);
    asm volatile("red.global.add.v4.f32 [%0], {%1, %2, %3, %4};"
                 :: "l"(o1), "f"(m1.x), "f"(m1.y), "f"(m1.z), "f"(m1.w) : "memory");
    asm volatile("red.global.add.v4.f32 [%0], {%1, %2, %3, %4};"
                 :: "l"(o2), "f"(m2.x), "f"(m2.y), "f"(m2.z), "f"(m2.w) : "memory");
}

// Node MLP as a register-tiled GEMM. Block = 128 nodes x 64 outputs,
// thread = 8 nodes x 4 outputs (16 f32x2 accumulators).
__global__ __launch_bounds__(NT, 2) void node_kernel(const float* __restrict__ W1g,
                                                     const float* __restrict__ b1g,
                                                     const float* __restrict__ W2g,
                                                     const float* __restrict__ b2g,
                                                     int n, int relu_out,
                                                     float* __restrict__ dout, int last) {
    extern __shared__ float sm[];
    float* sW1 = sm;                         // 64*WROW
    float* sW2 = sW1 + H * WROW;             // 64*WROW
    float* sb1 = sW2 + H * WROW;             // 64
    float* sb2 = sb1 + H;                    // 64
    float* sA  = sb2 + H;                    // 64*SROW (layer-1 input, k-major)
    float* sHm = sA + H * SROW;              // 64*SROW (h1, k-major)

    int tid = threadIdx.x;

    // Transposed weights: sW[k*WROW + j] = Wg[j*H + k]
    for (int idx = tid; idx < H * H; idx += NT) {
        int j = idx >> 6, k = idx & 63;
        sW1[k * WROW + j] = W1g[idx];
        sW2[k * WROW + j] = W2g[idx];
    }
    if (tid < H) { sb1[tid] = b1g[tid]; sb2[tid] = b2g[tid]; }

    int base = blockIdx.x * NPB;

    // Coalesced load of (x + agg); transpose+swizzle into sA; zero g_agg.
    for (int idx = tid; idx < NPB * (H / 4); idx += NT) {
        int row = idx >> 4;                  // node within tile
        int c   = (idx & 15) << 2;           // k base
        int g   = base + row;
        float4 v = make_float4(0.f, 0.f, 0.f, 0.f);
        if (g < n) {
            size_t off = (size_t)g * H + c;
            float4 xv = *(const float4*)(g_x + off);
            float4 av = *(const float4*)(g_agg + off);
            *(float4*)(g_agg + off) = make_float4(0.f, 0.f, 0.f, 0.f);
            v = make_float4(xv.x + av.x, xv.y + av.y, xv.z + av.z, xv.w + av.w);
        }
        sA[swiz(c + 0, row)] = v.x;
        sA[swiz(c + 1, row)] = v.y;
        sA[swiz(c + 2, row)] = v.z;
        sA[swiz(c + 3, row)] = v.w;
    }
    __syncthreads();

    int jIdx = tid & 15;                     // output-chunk index (varies in warp)
    int nIdx = tid >> 4;                     // node-chunk index (2 per warp)
    int j0 = jIdx * 4;
    int n0 = nIdx * 8;

    u64 acc[4][4];                           // [node-pair][jj]

    // ---- Layer 1: h1 = relu(W1 (x+agg) + b1) ----
    #pragma unroll
    for (int p = 0; p < 4; ++p)
        #pragma unroll
        for (int jj = 0; jj < 4; ++jj) acc[p][jj] = 0ull;

    #pragma unroll 4
    for (int k = 0; k < H; ++k) {
        const float* ap = sA + swiz(k, n0);
        ulonglong2 iA = *(const ulonglong2*)ap;        // node pairs 0,1
        ulonglong2 iB = *(const ulonglong2*)(ap + 4);  // node pairs 2,3
        float4 wv = *(const float4*)(sW1 + k * WROW + j0);
        u64 w0 = pk2(wv.x, wv.x), w1 = pk2(wv.y, wv.y);
        u64 w2 = pk2(wv.z, wv.z), w3 = pk2(wv.w, wv.w);
        acc[0][0] = ffma2(iA.x, w0, acc[0][0]);
        acc[0][1] = ffma2(iA.x, w1, acc[0][1]);
        acc[0][2] = ffma2(iA.x, w2, acc[0][2]);
        acc[0][3] = ffma2(iA.x, w3, acc[0][3]);
        acc[1][0] = ffma2(iA.y, w0, acc[1][0]);
        acc[1][1] = ffma2(iA.y, w1, acc[1][1]);
        acc[1][2] = ffma2(iA.y, w2, acc[1][2]);
        acc[1][3] = ffma2(iA.y, w3, acc[1][3]);
        acc[2][0] = ffma2(iB.x, w0, acc[2][0]);
        acc[2][1] = ffma2(iB.x, w1, acc[2][1]);
        acc[2][2] = ffma2(iB.x, w2, acc[2][2]);
        acc[2][3] = ffma2(iB.x, w3, acc[2][3]);
        acc[3][0] = ffma2(iB.y, w0, acc[3][0]);
        acc[3][1] = ffma2(iB.y, w1, acc[3][1]);
        acc[3][2] = ffma2(iB.y, w2, acc[3][2]);
        acc[3][3] = ffma2(iB.y, w3, acc[3][3]);
    }

    // h1 -> sHm (k-major over j), relu + bias
    #pragma unroll
    for (int jj = 0; jj < 4; ++jj) {
        float b = sb1[j0 + jj];
        float* hp = sHm + swiz(j0 + jj, n0);
        #pragma unroll
        for (int p = 0; p < 4; ++p) {
            float2 f = upk2(acc[p][jj]);
            hp[2 * p]     = fmaxf(f.x + b, 0.f);
            hp[2 * p + 1] = fmaxf(f.y + b, 0.f);
        }
    }
    __syncthreads();

    // ---- Layer 2: h2 = W2 h1 + b2 ----
    #pragma unroll
    for (int p = 0; p < 4; ++p)
        #pragma unroll
        for (int jj = 0; jj < 4; ++jj) acc[p][jj] = 0ull;

    #pragma unroll 4
    for (int k = 0; k < H; ++k) {
        const float* ap = sHm + swiz(k, n0);
        ulonglong2 iA = *(const ulonglong2*)ap;
        ulonglong2 iB = *(const ulonglong2*)(ap + 4);
        float4 wv = *(const float4*)(sW2 + k * WROW + j0);
        u64 w0 = pk2(wv.x, wv.x), w1 = pk2(wv.y, wv.y);
        u64 w2 = pk2(wv.z, wv.z), w3 = pk2(wv.w, wv.w);
        acc[0][0] = ffma2(iA.x, w0, acc[0][0]);
        acc[0][1] = ffma2(iA.x, w1, acc[0][1]);
        acc[0][2] = ffma2(iA.x, w2, acc[0][2]);
        acc[0][3] = ffma2(iA.x, w3, acc[0][3]);
        acc[1][0] = ffma2(iA.y, w0, acc[1][0]);
        acc[1][1] = ffma2(iA.y, w1, acc[1][1]);
        acc[1][2] = ffma2(iA.y, w2, acc[1][2]);
        acc[1][3] = ffma2(iA.y, w3, acc[1][3]);
        acc[2][0] = ffma2(iB.x, w0, acc[2][0]);
        acc[2][1] = ffma2(iB.x, w1, acc[2][1]);
        acc[2][2] = ffma2(iB.x, w2, acc[2][2]);
        acc[2][3] = ffma2(iB.x, w3, acc[2][3]);
        acc[3][0] = ffma2(iB.y, w0, acc[3][0]);
        acc[3][1] = ffma2(iB.y, w1, acc[3][1]);
        acc[3][2] = ffma2(iB.y, w2, acc[3][2]);
        acc[3][3] = ffma2(iB.y, w3, acc[3][3]);
    }

    // Epilogue: + b2, optional relu, + residual x, store (coalesced: each warp
    // covers 2 full 256B rows per q-step).
    float bb0 = sb2[j0], bb1 = sb2[j0 + 1], bb2v = sb2[j0 + 2], bb3 = sb2[j0 + 3];
    float* xout = last ? dout : g_x;
    #pragma unroll
    for (int q = 0; q < 8; ++q) {
        int g = base + n0 + q;
        if (g < n) {
            int p = q >> 1;
            float2 f0 = upk2(acc[p][0]), f1 = upk2(acc[p][1]);
            float2 f2 = upk2(acc[p][2]), f3 = upk2(acc[p][3]);
            float4 o;
            if ((q & 1) == 0) o = make_float4(f0.x + bb0, f1.x + bb1, f2.x + bb2v, f3.x + bb3);
            else              o = make_float4(f0.y + bb0, f1.y + bb1, f2.y + bb2v, f3.y + bb3);
            if (relu_out) {
                o.x = fmaxf(o.x, 0.f); o.y = fmaxf(o.y, 0.f);
                o.z = fmaxf(o.z, 0.f); o.w = fmaxf(o.w, 0.f);
            }
            size_t off = (size_t)g * H + j0;
            float4 res = *(const float4*)(g_x + off);
            o.x += res.x; o.y += res.y; o.z += res.z; o.w += res.w;
            *(float4*)(xout + off) = o;
        }
    }
}

static const int NODE_SMEM_BYTES =
    (2 * H * WROW + 2 * H + 2 * H * SROW) * (int)sizeof(float);

extern "C" void kernel_launch(void* const* d_in, const int* in_sizes, int n_in,
                              void* d_out, int out_size) {
    const float* node_emb  = (const float*)d_in[0];
    const float* W1        = (const float*)d_in[1];
    const float* b1        = (const float*)d_in[2];
    const float* W2        = (const float*)d_in[3];
    const float* b2        = (const float*)d_in[4];
    const float* edge_attr = (const float*)d_in[5];
    const int*   z         = (const int*)d_in[6];
    const int*   eidx      = (const int*)d_in[7];

    int n = in_sizes[6];        // 100000 nodes
    int E = in_sizes[7] / 2;    // 1000000 edges
    float* out = (float*)d_out;

    cudaFuncSetAttribute(node_kernel, cudaFuncAttributeMaxDynamicSharedMemorySize,
                         NODE_SMEM_BYTES);

    int nh = n / 2;
    init_kernel<<<(nh * (H / 4) + 255) / 256, 256>>>(node_emb, z, 0, nh);
    init_kernel<<<((n - nh) * (H / 4) + 255) / 256, 256>>>(node_emb, z, nh, n);

    int node_blocks = (n + NPB - 1) / NPB;
    int edge_blocks = ((E / 2) * 16 + 255) / 256;

    for (int i = 0; i < 3; ++i) {
        edge_kernel<<<edge_blocks, 256>>>(edge_attr, eidx, eidx + E, E);
        node_kernel<<<node_blocks, NT, NODE_SMEM_BYTES>>>(
            W1 + i * H * H, b1 + i * H, W2 + i * H * H, b2 + i * H,
            n, /*relu_out=*/(i < 2) ? 1 : 0, out, /*last=*/(i == 2) ? 1 : 0);
    }
}